// round 10
// baseline (speedup 1.0000x reference)
#include <cuda_runtime.h>
#include <cuda_bf16.h>
#include <stdint.h>

constexpr int B  = 2;
constexpr int S  = 2048;
constexpr int D  = 1024;
constexpr int H  = 16;
constexpr int DK = 64;
constexpr int M  = B * S;
constexpr long long OUT_ELEMS = (long long)B * S * D;
constexpr long long AW_ELEMS  = (long long)B * H * S * S;

// Scratch (device globals)
__device__ __nv_bfloat16 g_iqh[M * D], g_iql[M * D];
__device__ __nv_bfloat16 g_ikh[M * D], g_ikl[M * D];
__device__ __nv_bfloat16 g_ivh[M * D], g_ivl[M * D];
__device__ __nv_bfloat16 g_wqh[D * D], g_wql[D * D];
__device__ __nv_bfloat16 g_wkh[D * D], g_wkl[D * D];
__device__ __nv_bfloat16 g_wvh[D * D], g_wvl[D * D];
__device__ __nv_bfloat16 g_woh[D * D], g_wol[D * D];
__device__ __nv_bfloat16 g_qh[M * D], g_ql[M * D];
__device__ __nv_bfloat16 g_kh[M * D], g_kl[M * D];
__device__ __nv_bfloat16 g_vth[B * D * S], g_vtl[B * D * S];
__device__ __nv_bfloat16 g_cxh[M * D], g_cxl[M * D];
__device__ float g_out_spill[M * D];
__device__ float g_aw[B * H * S * S];
__device__ uint32_t g_pmask[B * S * (S / 32)];

// ---------------------------------------------------------------------------
__device__ __forceinline__ void mma16816(float c[4], const uint32_t a[4], const uint32_t b[2]) {
    asm volatile(
        "mma.sync.aligned.m16n8k16.row.col.f32.bf16.bf16.f32 "
        "{%0,%1,%2,%3}, {%4,%5,%6,%7}, {%8,%9}, {%0,%1,%2,%3};"
        : "+f"(c[0]), "+f"(c[1]), "+f"(c[2]), "+f"(c[3])
        : "r"(a[0]), "r"(a[1]), "r"(a[2]), "r"(a[3]), "r"(b[0]), "r"(b[1]));
}

__device__ __forceinline__ void split_f4(float4 v, uint2& hi, uint2& lo) {
    __nv_bfloat162 h01 = __floats2bfloat162_rn(v.x, v.y);
    __nv_bfloat162 h23 = __floats2bfloat162_rn(v.z, v.w);
    float2 f01 = __bfloat1622float2(h01);
    float2 f23 = __bfloat1622float2(h23);
    __nv_bfloat162 l01 = __floats2bfloat162_rn(v.x - f01.x, v.y - f01.y);
    __nv_bfloat162 l23 = __floats2bfloat162_rn(v.z - f23.x, v.w - f23.y);
    hi = make_uint2(*(uint32_t*)&h01, *(uint32_t*)&h23);
    lo = make_uint2(*(uint32_t*)&l01, *(uint32_t*)&l23);
}

__device__ __forceinline__ void cp16(void* sdst, const void* gsrc) {
    uint32_t sa = (uint32_t)__cvta_generic_to_shared(sdst);
    asm volatile("cp.async.cg.shared.global [%0], [%1], 16;" :: "r"(sa), "l"(gsrc));
}
#define CP_COMMIT() asm volatile("cp.async.commit_group;")
#define CP_WAIT1()  asm volatile("cp.async.wait_group 1;")
#define CP_WAIT0()  asm volatile("cp.async.wait_group 0;")

// ===========================================================================
__global__ __launch_bounds__(256) void pack_mask(const int* __restrict__ mask,
                                                 uint32_t* __restrict__ pm)
{
    const int warp = (blockIdx.x * blockDim.x + threadIdx.x) >> 5;
    const int lane = threadIdx.x & 31;
    const size_t base = (size_t)warp * 1024;
    #pragma unroll
    for (int i = 0; i < 32; i++) {
        int v = mask[base + i * 32 + lane];
        uint32_t w = __ballot_sync(0xFFFFFFFFu, v != 0);
        if (lane == i) pm[warp * 32 + i] = w;
    }
}

__global__ __launch_bounds__(256) void split_ew(const float* __restrict__ x,
                                                __nv_bfloat16* __restrict__ h,
                                                __nv_bfloat16* __restrict__ l, int n4)
{
    int i = blockIdx.x * blockDim.x + threadIdx.x;
    if (i >= n4) return;
    float4 v = ((const float4*)x)[i];
    uint2 hi, lo; split_f4(v, hi, lo);
    ((uint2*)h)[i] = hi;
    ((uint2*)l)[i] = lo;
}

// ===========================================================================
// Projection GEMM from PRE-SPLIT operands, cp.async 2-stage pipeline.
// ===========================================================================
constexpr int PJ_SMEM = 81920;

template<int OUT_MODE>
__global__ __launch_bounds__(256) void proj_ps(
    const __nv_bfloat16* __restrict__ xh, const __nv_bfloat16* __restrict__ xl,
    const __nv_bfloat16* __restrict__ wh, const __nv_bfloat16* __restrict__ wl,
    const float* __restrict__ bias, float* __restrict__ y,
    __nv_bfloat16* __restrict__ yh, __nv_bfloat16* __restrict__ yl)
{
    extern __shared__ unsigned char SM[];
    const int tid = threadIdx.x, lane = tid & 31, wrp = tid >> 5;
    const int n0 = blockIdx.x * 128, m0 = blockIdx.y * 128;
    const int wm = (wrp & 3) * 32, wn = (wrp >> 2) * 64;
    const int g = lane >> 2, t = lane & 3;

    float acc[2][8][4];
    #pragma unroll
    for (int i = 0; i < 2; i++)
        #pragma unroll
        for (int j = 0; j < 8; j++)
            #pragma unroll
            for (int r = 0; r < 4; r++) acc[i][j][r] = 0.0f;

    auto stage_load = [&](int kc, int s) {
        unsigned char* bb = SM + s * 40960;
        #pragma unroll
        for (int i = 0; i < 2; i++) {
            int f = tid + i * 256, row = f >> 2, c = f & 3;
            size_t xo = (size_t)(m0 + row) * 1024 + kc + c * 8;
            size_t wo = (size_t)(n0 + row) * 1024 + kc + c * 8;
            int so = row * 80 + c * 16;
            cp16(bb + so,         xh + xo);
            cp16(bb + 10240 + so, xl + xo);
            cp16(bb + 20480 + so, wh + wo);
            cp16(bb + 30720 + so, wl + wo);
        }
    };

    stage_load(0, 0); CP_COMMIT();

    for (int kc = 0; kc < 1024; kc += 32) {
        const int s = (kc >> 5) & 1;
        if (kc + 32 < 1024) { stage_load(kc + 32, s ^ 1); CP_COMMIT(); CP_WAIT1(); }
        else CP_WAIT0();
        __syncthreads();

        unsigned char* Ah = SM + s * 40960;
        unsigned char* Al = Ah + 10240;
        unsigned char* Bh = Ah + 20480;
        unsigned char* Bl = Ah + 30720;

        #pragma unroll
        for (int ks = 0; ks < 2; ks++) {
            const int off = ks * 32 + t * 4;
            uint32_t ah[2][4], al[2][4], bh[8][2], bl[8][2];
            #pragma unroll
            for (int mt = 0; mt < 2; mt++) {
                int r = wm + mt * 16 + g;
                ah[mt][0] = *(uint32_t*)(Ah + r * 80 + off);
                ah[mt][1] = *(uint32_t*)(Ah + (r + 8) * 80 + off);
                ah[mt][2] = *(uint32_t*)(Ah + r * 80 + off + 16);
                ah[mt][3] = *(uint32_t*)(Ah + (r + 8) * 80 + off + 16);
                al[mt][0] = *(uint32_t*)(Al + r * 80 + off);
                al[mt][1] = *(uint32_t*)(Al + (r + 8) * 80 + off);
                al[mt][2] = *(uint32_t*)(Al + r * 80 + off + 16);
                al[mt][3] = *(uint32_t*)(Al + (r + 8) * 80 + off + 16);
            }
            #pragma unroll
            for (int nt = 0; nt < 8; nt++) {
                int r = wn + nt * 8 + g;
                bh[nt][0] = *(uint32_t*)(Bh + r * 80 + off);
                bh[nt][1] = *(uint32_t*)(Bh + r * 80 + off + 16);
                bl[nt][0] = *(uint32_t*)(Bl + r * 80 + off);
                bl[nt][1] = *(uint32_t*)(Bl + r * 80 + off + 16);
            }
            #pragma unroll
            for (int mt = 0; mt < 2; mt++)
                #pragma unroll
                for (int nt = 0; nt < 8; nt++) {
                    mma16816(acc[mt][nt], ah[mt], bh[nt]);
                    mma16816(acc[mt][nt], ah[mt], bl[nt]);
                    mma16816(acc[mt][nt], al[mt], bh[nt]);
                }
        }
        __syncthreads();
    }

    if (OUT_MODE == 2) {
        __nv_bfloat16* THi = (__nv_bfloat16*)SM;            // [64][136]
        __nv_bfloat16* TLo = THi + 64 * 136;
        const int bb = m0 >> 11, s0 = m0 & 2047;
        #pragma unroll
        for (int half = 0; half < 2; half++) {
            if ((wrp >> 2) == half) {
                #pragma unroll
                for (int mt = 0; mt < 2; mt++)
                    #pragma unroll
                    for (int nt = 0; nt < 8; nt++) {
                        int row = wm + mt * 16 + g;
                        int cc  = nt * 8 + 2 * t;
                        float2 bv = *(const float2*)&bias[n0 + wn + nt * 8 + 2 * t];
                        float vv[4] = {acc[mt][nt][0] + bv.x, acc[mt][nt][1] + bv.y,
                                       acc[mt][nt][2] + bv.x, acc[mt][nt][3] + bv.y};
                        #pragma unroll
                        for (int e = 0; e < 4; e++) {
                            int r2 = row + (e >> 1) * 8;
                            int c2 = cc + (e & 1);
                            __nv_bfloat16 hb = __float2bfloat16(vv[e]);
                            __nv_bfloat16 lb = __float2bfloat16(vv[e] - __bfloat162float(hb));
                            THi[c2 * 136 + r2] = hb;
                            TLo[c2 * 136 + r2] = lb;
                        }
                    }
            }
            __syncthreads();
            #pragma unroll
            for (int i = 0; i < 4; i++) {
                int f = tid + i * 256, nn = f >> 4, ch = f & 15;
                uint4 vh = *(uint4*)&THi[nn * 136 + ch * 8];
                uint4 vl = *(uint4*)&TLo[nn * 136 + ch * 8];
                size_t gb = ((size_t)bb * D + n0 + half * 64 + nn) * S + s0 + ch * 8;
                *(uint4*)&yh[gb] = vh;
                *(uint4*)&yl[gb] = vl;
            }
            __syncthreads();
        }
        return;
    }

    #pragma unroll
    for (int mt = 0; mt < 2; mt++)
        #pragma unroll
        for (int nt = 0; nt < 8; nt++) {
            int row = m0 + wm + mt * 16 + g;
            int col = n0 + wn + nt * 8 + 2 * t;
            float2 bv = *(const float2*)&bias[col];
            float v0 = acc[mt][nt][0] + bv.x, v1 = acc[mt][nt][1] + bv.y;
            float v2 = acc[mt][nt][2] + bv.x, v3 = acc[mt][nt][3] + bv.y;
            if (OUT_MODE == 0) {
                *(float2*)&y[(size_t)row * 1024 + col] = make_float2(v0, v1);
                *(float2*)&y[(size_t)(row + 8) * 1024 + col] = make_float2(v2, v3);
            } else {
                __nv_bfloat162 h01 = __floats2bfloat162_rn(v0, v1);
                __nv_bfloat162 h23 = __floats2bfloat162_rn(v2, v3);
                float2 f01 = __bfloat1622float2(h01);
                float2 f23 = __bfloat1622float2(h23);
                __nv_bfloat162 l01 = __floats2bfloat162_rn(v0 - f01.x, v1 - f01.y);
                __nv_bfloat162 l23 = __floats2bfloat162_rn(v2 - f23.x, v3 - f23.y);
                *(__nv_bfloat162*)&yh[(size_t)row * 1024 + col] = h01;
                *(__nv_bfloat162*)&yh[(size_t)(row + 8) * 1024 + col] = h23;
                *(__nv_bfloat162*)&yl[(size_t)row * 1024 + col] = l01;
                *(__nv_bfloat162*)&yl[(size_t)(row + 8) * 1024 + col] = l23;
            }
        }
}

// ===========================================================================
// Fused scores + mask + streaming-exp softmax; cp.async 2-stage K pipeline.
// Block = 16 q-rows x full S, k-tile = 128 double-buffered.
// ===========================================================================
constexpr int SC_STRIDE = 2056;
constexpr int SC_BYTES  = 16 * SC_STRIDE * 4;                   // 131584
constexpr int QH_OFF = SC_BYTES,  QL_OFF = QH_OFF + 16 * 144;
constexpr int KS_OFF = QL_OFF + 16 * 144;                       // 136192
constexpr int KS_STRIDE = 128 * 144;                            // 18432 per buffer
// stage s: KH = KS_OFF + s*2*KS_STRIDE, KL = +KS_STRIDE
constexpr int PS_OFF = KS_OFF + 4 * KS_STRIDE;                  // 209920
constexpr int SMEM_SC = PS_OFF + 8 * 16 * 4;                    // 210432

__global__ __launch_bounds__(256) void scores_softmax(
    const __nv_bfloat16* __restrict__ qh, const __nv_bfloat16* __restrict__ ql,
    const __nv_bfloat16* __restrict__ kh, const __nv_bfloat16* __restrict__ kl,
    const uint32_t* __restrict__ pm, float* __restrict__ aw)
{
    extern __shared__ char sm[];
    float* sc = (float*)sm;
    unsigned char* Qh = (unsigned char*)sm + QH_OFF;
    unsigned char* Ql = (unsigned char*)sm + QL_OFF;
    float* psum = (float*)((unsigned char*)sm + PS_OFF);

    const int tid = threadIdx.x, lane = tid & 31, wrp = tid >> 5;
    const int q0 = blockIdx.x * 16;
    const int bh = blockIdx.y;
    const int b = bh >> 4, h = bh & 15;
    const size_t base = (size_t)b * S * D + (size_t)h * DK;
    const int g = lane >> 2, t = lane & 3;

    // Stage Q tile (regular loads; tiny)
    {
        int f = tid & 127, row = f >> 3, c = f & 7;
        const __nv_bfloat16* src = (tid < 128) ? qh : ql;
        unsigned char* dst = (tid < 128) ? Qh : Ql;
        uint4 v = *(const uint4*)&src[base + (size_t)(q0 + row) * 1024 + c * 8];
        *(uint4*)(dst + row * 144 + c * 16) = v;
    }

    // cp.async stage loader: k-tile of 128 rows x 64 d (hi+lo), 8 cp16/thread
    auto stage_load = [&](int tile, int s) {
        unsigned char* KH = (unsigned char*)sm + KS_OFF + s * 2 * KS_STRIDE;
        unsigned char* KL = KH + KS_STRIDE;
        const int n0 = tile * 128;
        #pragma unroll
        for (int i = 0; i < 4; i++) {
            int f = tid + i * 256, row = f >> 3, c = f & 7;
            size_t go = base + (size_t)(n0 + row) * 1024 + c * 8;
            int so = row * 144 + c * 16;
            cp16(KH + so, kh + go);
            cp16(KL + so, kl + go);
        }
    };

    const uint32_t* pmr0 = pm + ((size_t)b * S + q0 + g) * 64 + (wrp >> 1);
    const uint32_t* pmr1 = pm + ((size_t)b * S + q0 + g + 8) * 64 + (wrp >> 1);
    const int wbase = (wrp & 1) * 16;
    float sum0 = 0.0f, sum1 = 0.0f;

    stage_load(0, 0); CP_COMMIT();

    for (int tile = 0; tile < 16; tile++) {
        const int s = tile & 1;
        if (tile + 1 < 16) { stage_load(tile + 1, s ^ 1); CP_COMMIT(); CP_WAIT1(); }
        else CP_WAIT0();
        __syncthreads();

        unsigned char* KH = (unsigned char*)sm + KS_OFF + s * 2 * KS_STRIDE;
        unsigned char* KL = KH + KS_STRIDE;
        const int n0 = tile * 128;

        float acc[2][4];
        #pragma unroll
        for (int nt = 0; nt < 2; nt++)
            #pragma unroll
            for (int r = 0; r < 4; r++) acc[nt][r] = 0.0f;

        #pragma unroll
        for (int ks = 0; ks < 4; ks++) {
            const int off = ks * 32 + t * 4;
            uint32_t ah[4], al[4], bh2[2][2], bl2[2][2];
            ah[0] = *(uint32_t*)(Qh + g * 144 + off);
            ah[1] = *(uint32_t*)(Qh + (g + 8) * 144 + off);
            ah[2] = *(uint32_t*)(Qh + g * 144 + off + 16);
            ah[3] = *(uint32_t*)(Qh + (g + 8) * 144 + off + 16);
            al[0] = *(uint32_t*)(Ql + g * 144 + off);
            al[1] = *(uint32_t*)(Ql + (g + 8) * 144 + off);
            al[2] = *(uint32_t*)(Ql + g * 144 + off + 16);
            al[3] = *(uint32_t*)(Ql + (g + 8) * 144 + off + 16);
            #pragma unroll
            for (int nt = 0; nt < 2; nt++) {
                int r = wrp * 16 + nt * 8 + g;
                bh2[nt][0] = *(uint32_t*)(KH + r * 144 + off);
                bh2[nt][1] = *(uint32_t*)(KH + r * 144 + off + 16);
                bl2[nt][0] = *(uint32_t*)(KL + r * 144 + off);
                bl2[nt][1] = *(uint32_t*)(KL + r * 144 + off + 16);
            }
            #pragma unroll
            for (int nt = 0; nt < 2; nt++) {
                mma16816(acc[nt], ah, bh2[nt]);
                mma16816(acc[nt], ah, bl2[nt]);
                mma16816(acc[nt], al, bh2[nt]);
            }
        }

        // epilogue: scale + mask + exp + store + row sums
        const uint32_t mw0 = pmr0[n0 >> 5];
        const uint32_t mw1 = pmr1[n0 >> 5];
        #pragma unroll
        for (int nt = 0; nt < 2; nt++) {
            const int bit0 = wbase + nt * 8 + 2 * t, bit1 = bit0 + 1;
            float e00 = ((mw0 >> bit0) & 1u) ? 0.0f : __expf(acc[nt][0] * 0.125f);
            float e01 = ((mw0 >> bit1) & 1u) ? 0.0f : __expf(acc[nt][1] * 0.125f);
            float e10 = ((mw1 >> bit0) & 1u) ? 0.0f : __expf(acc[nt][2] * 0.125f);
            float e11 = ((mw1 >> bit1) & 1u) ? 0.0f : __expf(acc[nt][3] * 0.125f);
            sum0 += e00 + e01;
            sum1 += e10 + e11;
            int col = n0 + wrp * 16 + nt * 8 + 2 * t;
            *(float2*)&sc[g * SC_STRIDE + col]       = make_float2(e00, e01);
            *(float2*)&sc[(g + 8) * SC_STRIDE + col] = make_float2(e10, e11);
        }
        __syncthreads();
    }

    sum0 += __shfl_xor_sync(0xFFFFFFFFu, sum0, 1);
    sum0 += __shfl_xor_sync(0xFFFFFFFFu, sum0, 2);
    sum1 += __shfl_xor_sync(0xFFFFFFFFu, sum1, 1);
    sum1 += __shfl_xor_sync(0xFFFFFFFFu, sum1, 2);
    if (t == 0) {
        psum[wrp * 16 + g]     = sum0;
        psum[wrp * 16 + g + 8] = sum1;
    }
    __syncthreads();

    #pragma unroll
    for (int rr = 0; rr < 2; rr++) {
        const int r = wrp * 2 + rr, q = q0 + rr + wrp * 2 - wrp * 2 + wrp * 2;  // q0 + r
        float tot = 0.0f;
        #pragma unroll
        for (int wv = 0; wv < 8; wv++) tot += psum[wv * 16 + r];
        const float scale = (float)S / tot;
        const float4* s4 = (const float4*)&sc[r * SC_STRIDE];
        float4* a4 = (float4*)&aw[((size_t)bh * S + q0 + r) * S];
        #pragma unroll
        for (int i = 0; i < 16; i++) {
            float4 v = s4[i * 32 + lane];
            v.x *= scale; v.y *= scale; v.z *= scale; v.w *= scale;
            a4[i * 32 + lane] = v;
        }
    }
}

// ===========================================================================
// Ctx (R8 version, unchanged; epilogue emits split bf16).
// ===========================================================================
__global__ __launch_bounds__(256) void ctx_mma(
    const float* __restrict__ aw,
    const __nv_bfloat16* __restrict__ vth, const __nv_bfloat16* __restrict__ vtl,
    __nv_bfloat16* __restrict__ cxh, __nv_bfloat16* __restrict__ cxl)
{
    __shared__ unsigned char Ah[128 * 144], Al[128 * 144], Bh[64 * 144], Bl[64 * 144];
    const int tid = threadIdx.x, lane = tid & 31, wrp = tid >> 5;
    const int q0 = blockIdx.x * 128;
    const int bh = blockIdx.y;
    const int b = bh >> 4, h = bh & 15;
    const size_t vtbase = ((size_t)b * D + h * DK) * S;
    const int wm = (wrp & 3) * 32, wn = (wrp >> 2) * 32;
    const int g = lane >> 2, t = lane & 3;

    float acc[2][4][4];
    #pragma unroll
    for (int i = 0; i < 2; i++)
        #pragma unroll
        for (int j = 0; j < 4; j++)
            #pragma unroll
            for (int r = 0; r < 4; r++) acc[i][j][r] = 0.0f;

    for (int k0 = 0; k0 < S; k0 += 64) {
        #pragma unroll
        for (int i = 0; i < 8; i++) {
            int f = tid + i * 256, row = f >> 4, c = f & 15;
            float4 a = *(const float4*)&aw[((size_t)bh * S + q0 + row) * S + k0 + c * 4];
            uint2 hi, lo; split_f4(a, hi, lo);
            *(uint2*)(Ah + row * 144 + c * 8) = hi;
            *(uint2*)(Al + row * 144 + c * 8) = lo;
        }
        #pragma unroll
        for (int i = 0; i < 2; i++) {
            int f = tid + i * 256, row = f >> 3, c = f & 7;
            uint4 v = *(const uint4*)&vth[vtbase + (size_t)row * S + k0 + c * 8];
            *(uint4*)(Bh + row * 144 + c * 16) = v;
        }
        #pragma unroll
        for (int i = 0; i < 2; i++) {
            int f = tid + i * 256, row = f >> 3, c = f & 7;
            uint4 v = *(const uint4*)&vtl[vtbase + (size_t)row * S + k0 + c * 8];
            *(uint4*)(Bl + row * 144 + c * 16) = v;
        }
        __syncthreads();

        #pragma unroll
        for (int ks = 0; ks < 4; ks++) {
            const int off = ks * 32 + t * 4;
            uint32_t ah[2][4], al[2][4], bh2[4][2], bl2[4][2];
            #pragma unroll
            for (int mt = 0; mt < 2; mt++) {
                int r = wm + mt * 16 + g;
                ah[mt][0] = *(uint32_t*)(Ah + r * 144 + off);
                ah[mt][1] = *(uint32_t*)(Ah + (r + 8) * 144 + off);
                ah[mt][2] = *(uint32_t*)(Ah + r * 144 + off + 16);
                ah[mt][3] = *(uint32_t*)(Ah + (r + 8) * 144 + off + 16);
                al[mt][0] = *(uint32_t*)(Al + r * 144 + off);
                al[mt][1] = *(uint32_t*)(Al + (r + 8) * 144 + off);
                al[mt][2] = *(uint32_t*)(Al + r * 144 + off + 16);
                al[mt][3] = *(uint32_t*)(Al + (r + 8) * 144 + off + 16);
            }
            #pragma unroll
            for (int nt = 0; nt < 4; nt++) {
                int r = wn + nt * 8 + g;
                bh2[nt][0] = *(uint32_t*)(Bh + r * 144 + off);
                bh2[nt][1] = *(uint32_t*)(Bh + r * 144 + off + 16);
                bl2[nt][0] = *(uint32_t*)(Bl + r * 144 + off);
                bl2[nt][1] = *(uint32_t*)(Bl + r * 144 + off + 16);
            }
            #pragma unroll
            for (int mt = 0; mt < 2; mt++)
                #pragma unroll
                for (int nt = 0; nt < 4; nt++) {
                    mma16816(acc[mt][nt], ah[mt], bh2[nt]);
                    mma16816(acc[mt][nt], ah[mt], bl2[nt]);
                    mma16816(acc[mt][nt], al[mt], bh2[nt]);
                }
        }
        __syncthreads();
    }

    #pragma unroll
    for (int mt = 0; mt < 2; mt++)
        #pragma unroll
        for (int nt = 0; nt < 4; nt++) {
            int row = q0 + wm + mt * 16 + g;
            int col = wn + nt * 8 + 2 * t;
            size_t o0 = ((size_t)b * S + row) * D + h * DK + col;
            size_t o1 = ((size_t)b * S + row + 8) * D + h * DK + col;
            float v0 = acc[mt][nt][0], v1 = acc[mt][nt][1];
            float v2 = acc[mt][nt][2], v3 = acc[mt][nt][3];
            __nv_bfloat162 h01 = __floats2bfloat162_rn(v0, v1);
            __nv_bfloat162 h23 = __floats2bfloat162_rn(v2, v3);
            float2 f01 = __bfloat1622float2(h01);
            float2 f23 = __bfloat1622float2(h23);
            __nv_bfloat162 l01 = __floats2bfloat162_rn(v0 - f01.x, v1 - f01.y);
            __nv_bfloat162 l23 = __floats2bfloat162_rn(v2 - f23.x, v3 - f23.y);
            *(__nv_bfloat162*)&cxh[o0] = h01;
            *(__nv_bfloat162*)&cxl[o0] = l01;
            *(__nv_bfloat162*)&cxh[o1] = h23;
            *(__nv_bfloat162*)&cxl[o1] = l23;
        }
}

// ---------------------------------------------------------------------------
extern "C" void kernel_launch(void* const* d_in, const int* in_sizes, int n_in,
                              void* d_out, int out_size)
{
    const float* Q  = (const float*)d_in[0];
    const float* K_ = (const float*)d_in[1];
    const float* V  = (const float*)d_in[2];
    const int*   mask = (const int*)d_in[3];
    const float* Wq = (const float*)d_in[4];
    const float* bq = (const float*)d_in[5];
    const float* Wk = (const float*)d_in[6];
    const float* bk = (const float*)d_in[7];
    const float* Wv = (const float*)d_in[8];
    const float* bv = (const float*)d_in[9];
    const float* Wo = (const float*)d_in[10];
    const float* bo = (const float*)d_in[11];

    __nv_bfloat16 *iqh,*iql,*ikh,*ikl,*ivh,*ivl;
    __nv_bfloat16 *wqh,*wql,*wkh,*wkl,*wvh,*wvl,*woh,*wol;
    __nv_bfloat16 *qh,*ql,*kh,*kl,*vth,*vtl,*cxh,*cxl;
    float *gaw, *gspill;
    uint32_t* gpm;
    cudaGetSymbolAddress((void**)&iqh, g_iqh); cudaGetSymbolAddress((void**)&iql, g_iql);
    cudaGetSymbolAddress((void**)&ikh, g_ikh); cudaGetSymbolAddress((void**)&ikl, g_ikl);
    cudaGetSymbolAddress((void**)&ivh, g_ivh); cudaGetSymbolAddress((void**)&ivl, g_ivl);
    cudaGetSymbolAddress((void**)&wqh, g_wqh); cudaGetSymbolAddress((void**)&wql, g_wql);
    cudaGetSymbolAddress((void**)&wkh, g_wkh); cudaGetSymbolAddress((void**)&wkl, g_wkl);
    cudaGetSymbolAddress((void**)&wvh, g_wvh); cudaGetSymbolAddress((void**)&wvl, g_wvl);
    cudaGetSymbolAddress((void**)&woh, g_woh); cudaGetSymbolAddress((void**)&wol, g_wol);
    cudaGetSymbolAddress((void**)&qh,  g_qh);  cudaGetSymbolAddress((void**)&ql,  g_ql);
    cudaGetSymbolAddress((void**)&kh,  g_kh);  cudaGetSymbolAddress((void**)&kl,  g_kl);
    cudaGetSymbolAddress((void**)&vth, g_vth); cudaGetSymbolAddress((void**)&vtl, g_vtl);
    cudaGetSymbolAddress((void**)&cxh, g_cxh); cudaGetSymbolAddress((void**)&cxl, g_cxl);
    cudaGetSymbolAddress((void**)&gaw, g_aw);
    cudaGetSymbolAddress((void**)&gspill, g_out_spill);
    cudaGetSymbolAddress((void**)&gpm, g_pmask);

    float* out_ptr;
    float* aw_ptr;
    const long long osz = (long long)out_size;
    if (osz >= OUT_ELEMS + AW_ELEMS) {
        out_ptr = (float*)d_out;
        aw_ptr  = (float*)d_out + OUT_ELEMS;
    } else if (osz == AW_ELEMS) {
        out_ptr = gspill;
        aw_ptr  = (float*)d_out;
    } else {
        out_ptr = (float*)d_out;
        aw_ptr  = gaw;
    }

    cudaFuncSetAttribute(scores_softmax, cudaFuncAttributeMaxDynamicSharedMemorySize, SMEM_SC);
    cudaFuncSetAttribute(proj_ps<0>, cudaFuncAttributeMaxDynamicSharedMemorySize, PJ_SMEM);
    cudaFuncSetAttribute(proj_ps<1>, cudaFuncAttributeMaxDynamicSharedMemorySize, PJ_SMEM);
    cudaFuncSetAttribute(proj_ps<2>, cudaFuncAttributeMaxDynamicSharedMemorySize, PJ_SMEM);

    pack_mask<<<1024, 256>>>(mask, gpm);

    const int n4_in = M * D / 4, n4_w = D * D / 4;
    split_ew<<<n4_in / 256, 256>>>(Q,  iqh, iql, n4_in);
    split_ew<<<n4_in / 256, 256>>>(K_, ikh, ikl, n4_in);
    split_ew<<<n4_in / 256, 256>>>(V,  ivh, ivl, n4_in);
    split_ew<<<n4_w / 256, 256>>>(Wq, wqh, wql, n4_w);
    split_ew<<<n4_w / 256, 256>>>(Wk, wkh, wkl, n4_w);
    split_ew<<<n4_w / 256, 256>>>(Wv, wvh, wvl, n4_w);
    split_ew<<<n4_w / 256, 256>>>(Wo, woh, wol, n4_w);

    dim3 gProj(D / 128, M / 128);                  // (8, 32)
    proj_ps<1><<<gProj, 256, PJ_SMEM>>>(iqh, iql, wqh, wql, bq, nullptr, qh, ql);
    proj_ps<1><<<gProj, 256, PJ_SMEM>>>(ikh, ikl, wkh, wkl, bk, nullptr, kh, kl);
    proj_ps<2><<<gProj, 256, PJ_SMEM>>>(ivh, ivl, wvh, wvl, bv, nullptr, vth, vtl);

    dim3 gSc(S / 16, B * H);                       // (128, 32)
    scores_softmax<<<gSc, 256, SMEM_SC>>>(qh, ql, kh, kl, gpm, aw_ptr);

    dim3 gCx(S / 128, B * H);                      // (16, 32)
    ctx_mma<<<gCx, 256>>>(aw_ptr, vth, vtl, cxh, cxl);

    proj_ps<0><<<gProj, 256, PJ_SMEM>>>(cxh, cxl, woh, wol, bo, out_ptr, nullptr, nullptr);
}

// round 13
// speedup vs baseline: 1.5669x; 1.5669x over previous
#include <cuda_runtime.h>
#include <cuda_bf16.h>
#include <stdint.h>

constexpr int B  = 2;
constexpr int S  = 2048;
constexpr int D  = 1024;
constexpr int H  = 16;
constexpr int DK = 64;
constexpr int M  = B * S;
constexpr long long OUT_ELEMS = (long long)B * S * D;
constexpr long long AW_ELEMS  = (long long)B * H * S * S;

// Scratch (device globals)
__device__ __nv_bfloat16 g_qh[M * D], g_ql[M * D];
__device__ __nv_bfloat16 g_kh[M * D], g_kl[M * D];
__device__ __nv_bfloat16 g_vth[B * D * S], g_vtl[B * D * S];   // V^T: [B][D][S]
__device__ float g_ctx[M * D];
__device__ float g_out_spill[M * D];
__device__ float g_aw[B * H * S * S];
__device__ uint32_t g_pmask[B * S * (S / 32)];

// ---------------------------------------------------------------------------
__device__ __forceinline__ void mma16816(float c[4], const uint32_t a[4], const uint32_t b[2]) {
    asm volatile(
        "mma.sync.aligned.m16n8k16.row.col.f32.bf16.bf16.f32 "
        "{%0,%1,%2,%3}, {%4,%5,%6,%7}, {%8,%9}, {%0,%1,%2,%3};"
        : "+f"(c[0]), "+f"(c[1]), "+f"(c[2]), "+f"(c[3])
        : "r"(a[0]), "r"(a[1]), "r"(a[2]), "r"(a[3]), "r"(b[0]), "r"(b[1]));
}

// ldmatrix x4: 4 8x8 b16 tiles; lane groups 0-7/8-15/16-23/24-31 address tiles d0..d3.
__device__ __forceinline__ void ldsm_x4(uint32_t r[4], uint32_t saddr) {
    asm volatile("ldmatrix.sync.aligned.m8n8.x4.shared.b16 {%0,%1,%2,%3}, [%4];"
        : "=r"(r[0]), "=r"(r[1]), "=r"(r[2]), "=r"(r[3]) : "r"(saddr));
}

__device__ __forceinline__ uint32_t s2u(const void* p) {
    return (uint32_t)__cvta_generic_to_shared(p);
}

__device__ __forceinline__ void split_f4(float4 v, uint2& hi, uint2& lo) {
    __nv_bfloat162 h01 = __floats2bfloat162_rn(v.x, v.y);
    __nv_bfloat162 h23 = __floats2bfloat162_rn(v.z, v.w);
    float2 f01 = __bfloat1622float2(h01);
    float2 f23 = __bfloat1622float2(h23);
    __nv_bfloat162 l01 = __floats2bfloat162_rn(v.x - f01.x, v.y - f01.y);
    __nv_bfloat162 l23 = __floats2bfloat162_rn(v.z - f23.x, v.w - f23.y);
    hi = make_uint2(*(uint32_t*)&h01, *(uint32_t*)&h23);
    lo = make_uint2(*(uint32_t*)&l01, *(uint32_t*)&l23);
}

// Per-lane ldmatrix address components (A-type: 16 rows x 32B window)
struct LdsmIdx {
    int a_rel, a_col;     // row-in-tile + col half for A-type x4
    int b_rel, b_which, b_sub;  // for B-type paired x4
};
__device__ __forceinline__ LdsmIdx ldsm_idx(int lane) {
    LdsmIdx ix;
    ix.a_rel   = ((lane >> 3) & 1) * 8 + (lane & 7);
    ix.a_col   = (lane >> 4) * 16;
    ix.b_rel   = lane & 7;
    ix.b_which = lane >> 4;
    ix.b_sub   = ((lane >> 3) & 1) * 16;
    return ix;
}

// ===========================================================================
__global__ __launch_bounds__(256) void pack_mask(const int* __restrict__ mask,
                                                 uint32_t* __restrict__ pm)
{
    const int warp = (blockIdx.x * blockDim.x + threadIdx.x) >> 5;
    const int lane = threadIdx.x & 31;
    const size_t base = (size_t)warp * 1024;
    #pragma unroll
    for (int i = 0; i < 32; i++) {
        int v = mask[base + i * 32 + lane];
        uint32_t w = __ballot_sync(0xFFFFFFFFu, v != 0);
        if (lane == i) pm[warp * 32 + i] = w;
    }
}

// ===========================================================================
// Projection GEMM; OUT_MODE: 0 = f32 y, 1 = split bf16 hi/lo,
// 2 = split bf16 hi/lo TRANSPOSED ([B][D][S], for V) via smem transpose.
// ===========================================================================
template<int OUT_MODE>
__global__ __launch_bounds__(256) void proj_mma(
    const float* __restrict__ x, const float* __restrict__ w,
    const float* __restrict__ bias, float* __restrict__ y,
    __nv_bfloat16* __restrict__ yh, __nv_bfloat16* __restrict__ yl)
{
    __shared__ unsigned char SM[40960];
    unsigned char* Ah = SM;
    unsigned char* Al = SM + 10240;
    unsigned char* Bh = SM + 20480;
    unsigned char* Bl = SM + 30720;

    const int tid = threadIdx.x, lane = tid & 31, wrp = tid >> 5;
    const int n0 = blockIdx.x * 128, m0 = blockIdx.y * 128;
    const int wm = (wrp & 3) * 32, wn = (wrp >> 2) * 64;
    const int g = lane >> 2, t = lane & 3;

    float acc[2][8][4];
    #pragma unroll
    for (int i = 0; i < 2; i++)
        #pragma unroll
        for (int j = 0; j < 8; j++)
            #pragma unroll
            for (int r = 0; r < 4; r++) acc[i][j][r] = 0.0f;

    const LdsmIdx ix = ldsm_idx(lane);
    const uint32_t AhS = s2u(Ah), AlS = s2u(Al), BhS = s2u(Bh), BlS = s2u(Bl);
    uint32_t aoff[2], boff[4];
    #pragma unroll
    for (int mt = 0; mt < 2; mt++)
        aoff[mt] = (uint32_t)((wm + mt * 16 + ix.a_rel) * 80 + ix.a_col);
    #pragma unroll
    for (int p = 0; p < 4; p++)
        boff[p] = (uint32_t)((wn + (p * 2 + ix.b_which) * 8 + ix.b_rel) * 80 + ix.b_sub);

    for (int kc = 0; kc < 1024; kc += 32) {
        #pragma unroll
        for (int i = 0; i < 4; i++) {
            int f = tid + i * 256, row = f >> 3, c = f & 7;
            uint2 hi, lo;
            float4 v = *(const float4*)&x[(size_t)(m0 + row) * 1024 + kc + c * 4];
            split_f4(v, hi, lo);
            *(uint2*)(Ah + row * 80 + c * 8) = hi;
            *(uint2*)(Al + row * 80 + c * 8) = lo;
            float4 u = *(const float4*)&w[(size_t)(n0 + row) * 1024 + kc + c * 4];
            split_f4(u, hi, lo);
            *(uint2*)(Bh + row * 80 + c * 8) = hi;
            *(uint2*)(Bl + row * 80 + c * 8) = lo;
        }
        __syncthreads();

        #pragma unroll
        for (int ks = 0; ks < 2; ks++) {
            const int ko = ks * 32;
            uint32_t ah[2][4], al[2][4], bh[8][2], bl[8][2];
            #pragma unroll
            for (int mt = 0; mt < 2; mt++) {
                ldsm_x4(ah[mt], AhS + aoff[mt] + ko);
                ldsm_x4(al[mt], AlS + aoff[mt] + ko);
            }
            #pragma unroll
            for (int p = 0; p < 4; p++) {
                uint32_t r4[4];
                ldsm_x4(r4, BhS + boff[p] + ko);
                bh[2*p][0] = r4[0]; bh[2*p][1] = r4[1];
                bh[2*p+1][0] = r4[2]; bh[2*p+1][1] = r4[3];
                ldsm_x4(r4, BlS + boff[p] + ko);
                bl[2*p][0] = r4[0]; bl[2*p][1] = r4[1];
                bl[2*p+1][0] = r4[2]; bl[2*p+1][1] = r4[3];
            }
            #pragma unroll
            for (int mt = 0; mt < 2; mt++)
                #pragma unroll
                for (int nt = 0; nt < 8; nt++) {
                    mma16816(acc[mt][nt], ah[mt], bh[nt]);
                    mma16816(acc[mt][nt], ah[mt], bl[nt]);
                    mma16816(acc[mt][nt], al[mt], bh[nt]);
                }
        }
        __syncthreads();
    }

    if (OUT_MODE == 2) {
        __nv_bfloat16* THi = (__nv_bfloat16*)SM;            // [64][136]
        __nv_bfloat16* TLo = THi + 64 * 136;
        const int bb = m0 >> 11, s0 = m0 & 2047;
        #pragma unroll
        for (int half = 0; half < 2; half++) {
            if ((wrp >> 2) == half) {
                #pragma unroll
                for (int mt = 0; mt < 2; mt++)
                    #pragma unroll
                    for (int nt = 0; nt < 8; nt++) {
                        int row = wm + mt * 16 + g;
                        int cc  = nt * 8 + 2 * t;
                        float2 bv = *(const float2*)&bias[n0 + wn + nt * 8 + 2 * t];
                        float vv[4] = {acc[mt][nt][0] + bv.x, acc[mt][nt][1] + bv.y,
                                       acc[mt][nt][2] + bv.x, acc[mt][nt][3] + bv.y};
                        #pragma unroll
                        for (int e = 0; e < 4; e++) {
                            int r2 = row + (e >> 1) * 8;
                            int c2 = cc + (e & 1);
                            __nv_bfloat16 hb = __float2bfloat16(vv[e]);
                            __nv_bfloat16 lb = __float2bfloat16(vv[e] - __bfloat162float(hb));
                            THi[c2 * 136 + r2] = hb;
                            TLo[c2 * 136 + r2] = lb;
                        }
                    }
            }
            __syncthreads();
            #pragma unroll
            for (int i = 0; i < 4; i++) {
                int f = tid + i * 256, nn = f >> 4, ch = f & 15;
                uint4 vh = *(uint4*)&THi[nn * 136 + ch * 8];
                uint4 vl = *(uint4*)&TLo[nn * 136 + ch * 8];
                size_t gb = ((size_t)bb * D + n0 + half * 64 + nn) * S + s0 + ch * 8;
                *(uint4*)&yh[gb] = vh;
                *(uint4*)&yl[gb] = vl;
            }
            __syncthreads();
        }
        return;
    }

    #pragma unroll
    for (int mt = 0; mt < 2; mt++)
        #pragma unroll
        for (int nt = 0; nt < 8; nt++) {
            int row = m0 + wm + mt * 16 + g;
            int col = n0 + wn + nt * 8 + 2 * t;
            float2 bv = *(const float2*)&bias[col];
            float v0 = acc[mt][nt][0] + bv.x, v1 = acc[mt][nt][1] + bv.y;
            float v2 = acc[mt][nt][2] + bv.x, v3 = acc[mt][nt][3] + bv.y;
            if (OUT_MODE == 0) {
                *(float2*)&y[(size_t)row * 1024 + col] = make_float2(v0, v1);
                *(float2*)&y[(size_t)(row + 8) * 1024 + col] = make_float2(v2, v3);
            } else {
                __nv_bfloat162 h01 = __floats2bfloat162_rn(v0, v1);
                __nv_bfloat162 h23 = __floats2bfloat162_rn(v2, v3);
                float2 f01 = __bfloat1622float2(h01);
                float2 f23 = __bfloat1622float2(h23);
                __nv_bfloat162 l01 = __floats2bfloat162_rn(v0 - f01.x, v1 - f01.y);
                __nv_bfloat162 l23 = __floats2bfloat162_rn(v2 - f23.x, v3 - f23.y);
                *(__nv_bfloat162*)&yh[(size_t)row * 1024 + col] = h01;
                *(__nv_bfloat162*)&yh[(size_t)(row + 8) * 1024 + col] = h23;
                *(__nv_bfloat162*)&yl[(size_t)row * 1024 + col] = l01;
                *(__nv_bfloat162*)&yl[(size_t)(row + 8) * 1024 + col] = l23;
            }
        }
}

// ===========================================================================
// Fused scores + mask + streaming-exp softmax (R6 structure, LDSM frags).
// Block = 16 q x full S, k-tile 256, warp owns 32 k-cols (4 acc chains).
// ===========================================================================
constexpr int SC_STRIDE = 2056;
constexpr int SC_BYTES  = 16 * SC_STRIDE * 4;                   // 131584
constexpr int QH_OFF = SC_BYTES,  QL_OFF = QH_OFF + 16 * 144;
constexpr int KH_OFF = QL_OFF + 16 * 144;                       // 136192
constexpr int KL_OFF = KH_OFF + 256 * 144;                      // 173056
constexpr int PS_OFF = KL_OFF + 256 * 144;                      // 209920
constexpr int SMEM_SC = PS_OFF + 8 * 16 * 4;                    // 210432

__global__ __launch_bounds__(256) void scores_softmax(
    const __nv_bfloat16* __restrict__ qh, const __nv_bfloat16* __restrict__ ql,
    const __nv_bfloat16* __restrict__ kh, const __nv_bfloat16* __restrict__ kl,
    const uint32_t* __restrict__ pm, float* __restrict__ aw)
{
    extern __shared__ char sm[];
    float* sc = (float*)sm;
    unsigned char* Qh = (unsigned char*)sm + QH_OFF;
    unsigned char* Ql = (unsigned char*)sm + QL_OFF;
    unsigned char* Kh = (unsigned char*)sm + KH_OFF;
    unsigned char* Kl = (unsigned char*)sm + KL_OFF;
    float* psum = (float*)((unsigned char*)sm + PS_OFF);

    const int tid = threadIdx.x, lane = tid & 31, wrp = tid >> 5;
    const int q0 = blockIdx.x * 16;
    const int bh = blockIdx.y;
    const int b = bh >> 4, h = bh & 15;
    const size_t base = (size_t)b * S * D + (size_t)h * DK;
    const int g = lane >> 2, t = lane & 3;

    {
        int f = tid & 127, row = f >> 3, c = f & 7;
        const __nv_bfloat16* src = (tid < 128) ? qh : ql;
        unsigned char* dst = (tid < 128) ? Qh : Ql;
        uint4 v = *(const uint4*)&src[base + (size_t)(q0 + row) * 1024 + c * 8];
        *(uint4*)(dst + row * 144 + c * 16) = v;
    }

    const LdsmIdx ix = ldsm_idx(lane);
    const uint32_t QhS = s2u(Qh), QlS = s2u(Ql), KhS = s2u(Kh), KlS = s2u(Kl);
    const uint32_t aoff = (uint32_t)(ix.a_rel * 144 + ix.a_col);
    uint32_t boff[2];
    #pragma unroll
    for (int p = 0; p < 2; p++)
        boff[p] = (uint32_t)((wrp * 32 + (p * 2 + ix.b_which) * 8 + ix.b_rel) * 144 + ix.b_sub);

    const uint32_t* pmr0 = pm + ((size_t)b * S + q0 + g) * 64 + wrp;
    const uint32_t* pmr1 = pm + ((size_t)b * S + q0 + g + 8) * 64 + wrp;
    float sum0 = 0.0f, sum1 = 0.0f;

    for (int n0 = 0; n0 < S; n0 += 256) {
        #pragma unroll
        for (int i = 0; i < 8; i++) {
            int f = tid + i * 256, row = f >> 3, c = f & 7;
            uint4 v = *(const uint4*)&kh[base + (size_t)(n0 + row) * 1024 + c * 8];
            *(uint4*)(Kh + row * 144 + c * 16) = v;
        }
        #pragma unroll
        for (int i = 0; i < 8; i++) {
            int f = tid + i * 256, row = f >> 3, c = f & 7;
            uint4 v = *(const uint4*)&kl[base + (size_t)(n0 + row) * 1024 + c * 8];
            *(uint4*)(Kl + row * 144 + c * 16) = v;
        }
        __syncthreads();

        float acc[4][4];
        #pragma unroll
        for (int nt = 0; nt < 4; nt++)
            #pragma unroll
            for (int r = 0; r < 4; r++) acc[nt][r] = 0.0f;

        #pragma unroll
        for (int ks = 0; ks < 4; ks++) {
            const int ko = ks * 32;
            uint32_t ah[4], al[4], bh2[4][2], bl2[4][2];
            ldsm_x4(ah, QhS + aoff + ko);
            ldsm_x4(al, QlS + aoff + ko);
            #pragma unroll
            for (int p = 0; p < 2; p++) {
                uint32_t r4[4];
                ldsm_x4(r4, KhS + boff[p] + ko);
                bh2[2*p][0] = r4[0]; bh2[2*p][1] = r4[1];
                bh2[2*p+1][0] = r4[2]; bh2[2*p+1][1] = r4[3];
                ldsm_x4(r4, KlS + boff[p] + ko);
                bl2[2*p][0] = r4[0]; bl2[2*p][1] = r4[1];
                bl2[2*p+1][0] = r4[2]; bl2[2*p+1][1] = r4[3];
            }
            #pragma unroll
            for (int nt = 0; nt < 4; nt++) {
                mma16816(acc[nt], ah, bh2[nt]);
                mma16816(acc[nt], ah, bl2[nt]);
                mma16816(acc[nt], al, bh2[nt]);
            }
        }

        const uint32_t mw0 = pmr0[n0 >> 5];
        const uint32_t mw1 = pmr1[n0 >> 5];
        #pragma unroll
        for (int nt = 0; nt < 4; nt++) {
            const int bit0 = nt * 8 + 2 * t, bit1 = bit0 + 1;
            float e00 = ((mw0 >> bit0) & 1u) ? 0.0f : __expf(acc[nt][0] * 0.125f);
            float e01 = ((mw0 >> bit1) & 1u) ? 0.0f : __expf(acc[nt][1] * 0.125f);
            float e10 = ((mw1 >> bit0) & 1u) ? 0.0f : __expf(acc[nt][2] * 0.125f);
            float e11 = ((mw1 >> bit1) & 1u) ? 0.0f : __expf(acc[nt][3] * 0.125f);
            sum0 += e00 + e01;
            sum1 += e10 + e11;
            int col = n0 + wrp * 32 + nt * 8 + 2 * t;
            *(float2*)&sc[g * SC_STRIDE + col]       = make_float2(e00, e01);
            *(float2*)&sc[(g + 8) * SC_STRIDE + col] = make_float2(e10, e11);
        }
        __syncthreads();
    }

    sum0 += __shfl_xor_sync(0xFFFFFFFFu, sum0, 1);
    sum0 += __shfl_xor_sync(0xFFFFFFFFu, sum0, 2);
    sum1 += __shfl_xor_sync(0xFFFFFFFFu, sum1, 1);
    sum1 += __shfl_xor_sync(0xFFFFFFFFu, sum1, 2);
    if (t == 0) {
        psum[wrp * 16 + g]     = sum0;
        psum[wrp * 16 + g + 8] = sum1;
    }
    __syncthreads();

    #pragma unroll
    for (int rr = 0; rr < 2; rr++) {
        const int r = wrp * 2 + rr, q = q0 + r;
        float tot = 0.0f;
        #pragma unroll
        for (int wv = 0; wv < 8; wv++) tot += psum[wv * 16 + r];
        const float scale = (float)S / tot;
        const float4* s4 = (const float4*)&sc[r * SC_STRIDE];
        float4* a4 = (float4*)&aw[((size_t)bh * S + q) * S];
        #pragma unroll
        for (int i = 0; i < 16; i++) {
            float4 v = s4[i * 32 + lane];
            v.x *= scale; v.y *= scale; v.z *= scale; v.w *= scale;
            a4[i * 32 + lane] = v;
        }
    }
}

// ===========================================================================
// Ctx: block 128q x 64d, K-chunk 64 (R6 structure, LDSM frags).
// ===========================================================================
__global__ __launch_bounds__(256) void ctx_mma(
    const float* __restrict__ aw,
    const __nv_bfloat16* __restrict__ vth, const __nv_bfloat16* __restrict__ vtl,
    float* __restrict__ ctx)
{
    __shared__ unsigned char Ah[128 * 144], Al[128 * 144], Bh[64 * 144], Bl[64 * 144];
    const int tid = threadIdx.x, lane = tid & 31, wrp = tid >> 5;
    const int q0 = blockIdx.x * 128;
    const int bh = blockIdx.y;
    const int b = bh >> 4, h = bh & 15;
    const size_t vtbase = ((size_t)b * D + h * DK) * S;
    const int wm = (wrp & 3) * 32, wn = (wrp >> 2) * 32;
    const int g = lane >> 2, t = lane & 3;

    float acc[2][4][4];
    #pragma unroll
    for (int i = 0; i < 2; i++)
        #pragma unroll
        for (int j = 0; j < 4; j++)
            #pragma unroll
            for (int r = 0; r < 4; r++) acc[i][j][r] = 0.0f;

    const LdsmIdx ix = ldsm_idx(lane);
    const uint32_t AhS = s2u(Ah), AlS = s2u(Al), BhS = s2u(Bh), BlS = s2u(Bl);
    uint32_t aoff[2], boff[2];
    #pragma unroll
    for (int mt = 0; mt < 2; mt++)
        aoff[mt] = (uint32_t)((wm + mt * 16 + ix.a_rel) * 144 + ix.a_col);
    #pragma unroll
    for (int p = 0; p < 2; p++)
        boff[p] = (uint32_t)((wn + (p * 2 + ix.b_which) * 8 + ix.b_rel) * 144 + ix.b_sub);

    for (int k0 = 0; k0 < S; k0 += 64) {
        #pragma unroll
        for (int i = 0; i < 8; i++) {
            int f = tid + i * 256, row = f >> 4, c = f & 15;
            float4 a = *(const float4*)&aw[((size_t)bh * S + q0 + row) * S + k0 + c * 4];
            uint2 hi, lo; split_f4(a, hi, lo);
            *(uint2*)(Ah + row * 144 + c * 8) = hi;
            *(uint2*)(Al + row * 144 + c * 8) = lo;
        }
        #pragma unroll
        for (int i = 0; i < 2; i++) {
            int f = tid + i * 256, row = f >> 3, c = f & 7;
            uint4 v = *(const uint4*)&vth[vtbase + (size_t)row * S + k0 + c * 8];
            *(uint4*)(Bh + row * 144 + c * 16) = v;
        }
        #pragma unroll
        for (int i = 0; i < 2; i++) {
            int f = tid + i * 256, row = f >> 3, c = f & 7;
            uint4 v = *(const uint4*)&vtl[vtbase + (size_t)row * S + k0 + c * 8];
            *(uint4*)(Bl + row * 144 + c * 16) = v;
        }
        __syncthreads();

        #pragma unroll
        for (int ks = 0; ks < 4; ks++) {
            const int ko = ks * 32;
            uint32_t ah[2][4], al[2][4], bh2[4][2], bl2[4][2];
            #pragma unroll
            for (int mt = 0; mt < 2; mt++) {
                ldsm_x4(ah[mt], AhS + aoff[mt] + ko);
                ldsm_x4(al[mt], AlS + aoff[mt] + ko);
            }
            #pragma unroll
            for (int p = 0; p < 2; p++) {
                uint32_t r4[4];
                ldsm_x4(r4, BhS + boff[p] + ko);
                bh2[2*p][0] = r4[0]; bh2[2*p][1] = r4[1];
                bh2[2*p+1][0] = r4[2]; bh2[2*p+1][1] = r4[3];
                ldsm_x4(r4, BlS + boff[p] + ko);
                bl2[2*p][0] = r4[0]; bl2[2*p][1] = r4[1];
                bl2[2*p+1][0] = r4[2]; bl2[2*p+1][1] = r4[3];
            }
            #pragma unroll
            for (int mt = 0; mt < 2; mt++)
                #pragma unroll
                for (int nt = 0; nt < 4; nt++) {
                    mma16816(acc[mt][nt], ah[mt], bh2[nt]);
                    mma16816(acc[mt][nt], ah[mt], bl2[nt]);
                    mma16816(acc[mt][nt], al[mt], bh2[nt]);
                }
        }
        __syncthreads();
    }

    #pragma unroll
    for (int mt = 0; mt < 2; mt++)
        #pragma unroll
        for (int nt = 0; nt < 4; nt++) {
            int row = q0 + wm + mt * 16 + g;
            int col = wn + nt * 8 + 2 * t;
            *(float2*)&ctx[((size_t)b * S + row) * 1024 + h * DK + col] =
                make_float2(acc[mt][nt][0], acc[mt][nt][1]);
            *(float2*)&ctx[((size_t)b * S + row + 8) * 1024 + h * DK + col] =
                make_float2(acc[mt][nt][2], acc[mt][nt][3]);
        }
}

// ---------------------------------------------------------------------------
extern "C" void kernel_launch(void* const* d_in, const int* in_sizes, int n_in,
                              void* d_out, int out_size)
{
    const float* Q  = (const float*)d_in[0];
    const float* K_ = (const float*)d_in[1];
    const float* V  = (const float*)d_in[2];
    const int*   mask = (const int*)d_in[3];
    const float* Wq = (const float*)d_in[4];
    const float* bq = (const float*)d_in[5];
    const float* Wk = (const float*)d_in[6];
    const float* bk = (const float*)d_in[7];
    const float* Wv = (const float*)d_in[8];
    const float* bv = (const float*)d_in[9];
    const float* Wo = (const float*)d_in[10];
    const float* bo = (const float*)d_in[11];

    __nv_bfloat16 *qh, *ql, *kh, *kl, *vth, *vtl;
    float *gctx, *gaw, *gspill;
    uint32_t* gpm;
    cudaGetSymbolAddress((void**)&qh,   g_qh);
    cudaGetSymbolAddress((void**)&ql,   g_ql);
    cudaGetSymbolAddress((void**)&kh,   g_kh);
    cudaGetSymbolAddress((void**)&kl,   g_kl);
    cudaGetSymbolAddress((void**)&vth,  g_vth);
    cudaGetSymbolAddress((void**)&vtl,  g_vtl);
    cudaGetSymbolAddress((void**)&gctx, g_ctx);
    cudaGetSymbolAddress((void**)&gaw,  g_aw);
    cudaGetSymbolAddress((void**)&gspill, g_out_spill);
    cudaGetSymbolAddress((void**)&gpm,  g_pmask);

    float* out_ptr;
    float* aw_ptr;
    const long long osz = (long long)out_size;
    if (osz >= OUT_ELEMS + AW_ELEMS) {
        out_ptr = (float*)d_out;
        aw_ptr  = (float*)d_out + OUT_ELEMS;
    } else if (osz == AW_ELEMS) {
        out_ptr = gspill;
        aw_ptr  = (float*)d_out;
    } else {
        out_ptr = (float*)d_out;
        aw_ptr  = gaw;
    }

    cudaFuncSetAttribute(scores_softmax, cudaFuncAttributeMaxDynamicSharedMemorySize, SMEM_SC);

    pack_mask<<<1024, 256>>>(mask, gpm);

    dim3 gProj(D / 128, M / 128);                  // (8, 32)
    proj_mma<1><<<gProj, 256>>>(Q,  Wq, bq, nullptr, qh, ql);
    proj_mma<1><<<gProj, 256>>>(K_, Wk, bk, nullptr, kh, kl);
    proj_mma<2><<<gProj, 256>>>(V,  Wv, bv, nullptr, vth, vtl);

    dim3 gSc(S / 16, B * H);                       // (128, 32)
    scores_softmax<<<gSc, 256, SMEM_SC>>>(qh, ql, kh, kl, gpm, aw_ptr);

    dim3 gCx(S / 128, B * H);                      // (16, 32)
    ctx_mma<<<gCx, 256>>>(aw_ptr, vth, vtl, gctx);

    proj_mma<0><<<gProj, 256>>>(gctx, Wo, bo, out_ptr, nullptr, nullptr);
}

// round 17
// speedup vs baseline: 1.6491x; 1.0525x over previous
#include <cuda_runtime.h>
#include <cuda_bf16.h>
#include <cuda_fp16.h>
#include <stdint.h>

constexpr int B  = 2;
constexpr int S  = 2048;
constexpr int D  = 1024;
constexpr int H  = 16;
constexpr int DK = 64;
constexpr int M  = B * S;
constexpr long long OUT_ELEMS = (long long)B * S * D;
constexpr long long AW_ELEMS  = (long long)B * H * S * S;

// Scratch (device globals)
__device__ __nv_bfloat16 g_qh[M * D], g_ql[M * D];
__device__ __nv_bfloat16 g_kh[M * D], g_kl[M * D];
__device__ __nv_bfloat16 g_vth[B * D * S], g_vtl[B * D * S];   // V^T: [B][D][S]
__device__ float g_ctx[M * D];
__device__ float g_out_spill[M * D];
__device__ float g_aw[B * H * S * S];
__device__ uint32_t g_pmask[B * S * (S / 32)];

// ---------------------------------------------------------------------------
__device__ __forceinline__ void mma16816(float c[4], const uint32_t a[4], const uint32_t b[2]) {
    asm volatile(
        "mma.sync.aligned.m16n8k16.row.col.f32.bf16.bf16.f32 "
        "{%0,%1,%2,%3}, {%4,%5,%6,%7}, {%8,%9}, {%0,%1,%2,%3};"
        : "+f"(c[0]), "+f"(c[1]), "+f"(c[2]), "+f"(c[3])
        : "r"(a[0]), "r"(a[1]), "r"(a[2]), "r"(a[3]), "r"(b[0]), "r"(b[1]));
}

__device__ __forceinline__ void ldsm_x4(uint32_t r[4], uint32_t saddr) {
    asm volatile("ldmatrix.sync.aligned.m8n8.x4.shared.b16 {%0,%1,%2,%3}, [%4];"
        : "=r"(r[0]), "=r"(r[1]), "=r"(r[2]), "=r"(r[3]) : "r"(saddr));
}

__device__ __forceinline__ uint32_t s2u(const void* p) {
    return (uint32_t)__cvta_generic_to_shared(p);
}

__device__ __forceinline__ void split_f4(float4 v, uint2& hi, uint2& lo) {
    __nv_bfloat162 h01 = __floats2bfloat162_rn(v.x, v.y);
    __nv_bfloat162 h23 = __floats2bfloat162_rn(v.z, v.w);
    float2 f01 = __bfloat1622float2(h01);
    float2 f23 = __bfloat1622float2(h23);
    __nv_bfloat162 l01 = __floats2bfloat162_rn(v.x - f01.x, v.y - f01.y);
    __nv_bfloat162 l23 = __floats2bfloat162_rn(v.z - f23.x, v.w - f23.y);
    hi = make_uint2(*(uint32_t*)&h01, *(uint32_t*)&h23);
    lo = make_uint2(*(uint32_t*)&l01, *(uint32_t*)&l23);
}

struct LdsmIdx {
    int a_rel, a_col;
    int b_rel, b_which, b_sub;
};
__device__ __forceinline__ LdsmIdx ldsm_idx(int lane) {
    LdsmIdx ix;
    ix.a_rel   = ((lane >> 3) & 1) * 8 + (lane & 7);
    ix.a_col   = (lane >> 4) * 16;
    ix.b_rel   = lane & 7;
    ix.b_which = lane >> 4;
    ix.b_sub   = ((lane >> 3) & 1) * 16;
    return ix;
}

// ===========================================================================
__global__ __launch_bounds__(256) void pack_mask(const int* __restrict__ mask,
                                                 uint32_t* __restrict__ pm)
{
    const int warp = (blockIdx.x * blockDim.x + threadIdx.x) >> 5;
    const int lane = threadIdx.x & 31;
    const size_t base = (size_t)warp * 1024;
    #pragma unroll
    for (int i = 0; i < 32; i++) {
        int v = mask[base + i * 32 + lane];
        uint32_t w = __ballot_sync(0xFFFFFFFFu, v != 0);
        if (lane == i) pm[warp * 32 + i] = w;
    }
}

// ===========================================================================
// Projection GEMM (R13, unchanged). OUT_MODE: 0=f32, 1=split, 2=split-T.
// ===========================================================================
template<int OUT_MODE>
__global__ __launch_bounds__(256) void proj_mma(
    const float* __restrict__ x, const float* __restrict__ w,
    const float* __restrict__ bias, float* __restrict__ y,
    __nv_bfloat16* __restrict__ yh, __nv_bfloat16* __restrict__ yl)
{
    __shared__ unsigned char SM[40960];
    unsigned char* Ah = SM;
    unsigned char* Al = SM + 10240;
    unsigned char* Bh = SM + 20480;
    unsigned char* Bl = SM + 30720;

    const int tid = threadIdx.x, lane = tid & 31, wrp = tid >> 5;
    const int n0 = blockIdx.x * 128, m0 = blockIdx.y * 128;
    const int wm = (wrp & 3) * 32, wn = (wrp >> 2) * 64;
    const int g = lane >> 2, t = lane & 3;

    float acc[2][8][4];
    #pragma unroll
    for (int i = 0; i < 2; i++)
        #pragma unroll
        for (int j = 0; j < 8; j++)
            #pragma unroll
            for (int r = 0; r < 4; r++) acc[i][j][r] = 0.0f;

    const LdsmIdx ix = ldsm_idx(lane);
    const uint32_t AhS = s2u(Ah), AlS = s2u(Al), BhS = s2u(Bh), BlS = s2u(Bl);
    uint32_t aoff[2], boff[4];
    #pragma unroll
    for (int mt = 0; mt < 2; mt++)
        aoff[mt] = (uint32_t)((wm + mt * 16 + ix.a_rel) * 80 + ix.a_col);
    #pragma unroll
    for (int p = 0; p < 4; p++)
        boff[p] = (uint32_t)((wn + (p * 2 + ix.b_which) * 8 + ix.b_rel) * 80 + ix.b_sub);

    for (int kc = 0; kc < 1024; kc += 32) {
        #pragma unroll
        for (int i = 0; i < 4; i++) {
            int f = tid + i * 256, row = f >> 3, c = f & 7;
            uint2 hi, lo;
            float4 v = *(const float4*)&x[(size_t)(m0 + row) * 1024 + kc + c * 4];
            split_f4(v, hi, lo);
            *(uint2*)(Ah + row * 80 + c * 8) = hi;
            *(uint2*)(Al + row * 80 + c * 8) = lo;
            float4 u = *(const float4*)&w[(size_t)(n0 + row) * 1024 + kc + c * 4];
            split_f4(u, hi, lo);
            *(uint2*)(Bh + row * 80 + c * 8) = hi;
            *(uint2*)(Bl + row * 80 + c * 8) = lo;
        }
        __syncthreads();

        #pragma unroll
        for (int ks = 0; ks < 2; ks++) {
            const int ko = ks * 32;
            uint32_t ah[2][4], al[2][4], bh[8][2], bl[8][2];
            #pragma unroll
            for (int mt = 0; mt < 2; mt++) {
                ldsm_x4(ah[mt], AhS + aoff[mt] + ko);
                ldsm_x4(al[mt], AlS + aoff[mt] + ko);
            }
            #pragma unroll
            for (int p = 0; p < 4; p++) {
                uint32_t r4[4];
                ldsm_x4(r4, BhS + boff[p] + ko);
                bh[2*p][0] = r4[0]; bh[2*p][1] = r4[1];
                bh[2*p+1][0] = r4[2]; bh[2*p+1][1] = r4[3];
                ldsm_x4(r4, BlS + boff[p] + ko);
                bl[2*p][0] = r4[0]; bl[2*p][1] = r4[1];
                bl[2*p+1][0] = r4[2]; bl[2*p+1][1] = r4[3];
            }
            #pragma unroll
            for (int mt = 0; mt < 2; mt++)
                #pragma unroll
                for (int nt = 0; nt < 8; nt++) {
                    mma16816(acc[mt][nt], ah[mt], bh[nt]);
                    mma16816(acc[mt][nt], ah[mt], bl[nt]);
                    mma16816(acc[mt][nt], al[mt], bh[nt]);
                }
        }
        __syncthreads();
    }

    if (OUT_MODE == 2) {
        __nv_bfloat16* THi = (__nv_bfloat16*)SM;            // [64][136]
        __nv_bfloat16* TLo = THi + 64 * 136;
        const int bb = m0 >> 11, s0 = m0 & 2047;
        #pragma unroll
        for (int half = 0; half < 2; half++) {
            if ((wrp >> 2) == half) {
                #pragma unroll
                for (int mt = 0; mt < 2; mt++)
                    #pragma unroll
                    for (int nt = 0; nt < 8; nt++) {
                        int row = wm + mt * 16 + g;
                        int cc  = nt * 8 + 2 * t;
                        float2 bv = *(const float2*)&bias[n0 + wn + nt * 8 + 2 * t];
                        float vv[4] = {acc[mt][nt][0] + bv.x, acc[mt][nt][1] + bv.y,
                                       acc[mt][nt][2] + bv.x, acc[mt][nt][3] + bv.y};
                        #pragma unroll
                        for (int e = 0; e < 4; e++) {
                            int r2 = row + (e >> 1) * 8;
                            int c2 = cc + (e & 1);
                            __nv_bfloat16 hb = __float2bfloat16(vv[e]);
                            __nv_bfloat16 lb = __float2bfloat16(vv[e] - __bfloat162float(hb));
                            THi[c2 * 136 + r2] = hb;
                            TLo[c2 * 136 + r2] = lb;
                        }
                    }
            }
            __syncthreads();
            #pragma unroll
            for (int i = 0; i < 4; i++) {
                int f = tid + i * 256, nn = f >> 4, ch = f & 15;
                uint4 vh = *(uint4*)&THi[nn * 136 + ch * 8];
                uint4 vl = *(uint4*)&TLo[nn * 136 + ch * 8];
                size_t gb = ((size_t)bb * D + n0 + half * 64 + nn) * S + s0 + ch * 8;
                *(uint4*)&yh[gb] = vh;
                *(uint4*)&yl[gb] = vl;
            }
            __syncthreads();
        }
        return;
    }

    #pragma unroll
    for (int mt = 0; mt < 2; mt++)
        #pragma unroll
        for (int nt = 0; nt < 8; nt++) {
            int row = m0 + wm + mt * 16 + g;
            int col = n0 + wn + nt * 8 + 2 * t;
            float2 bv = *(const float2*)&bias[col];
            float v0 = acc[mt][nt][0] + bv.x, v1 = acc[mt][nt][1] + bv.y;
            float v2 = acc[mt][nt][2] + bv.x, v3 = acc[mt][nt][3] + bv.y;
            if (OUT_MODE == 0) {
                *(float2*)&y[(size_t)row * 1024 + col] = make_float2(v0, v1);
                *(float2*)&y[(size_t)(row + 8) * 1024 + col] = make_float2(v2, v3);
            } else {
                __nv_bfloat162 h01 = __floats2bfloat162_rn(v0, v1);
                __nv_bfloat162 h23 = __floats2bfloat162_rn(v2, v3);
                float2 f01 = __bfloat1622float2(h01);
                float2 f23 = __bfloat1622float2(h23);
                __nv_bfloat162 l01 = __floats2bfloat162_rn(v0 - f01.x, v1 - f01.y);
                __nv_bfloat162 l23 = __floats2bfloat162_rn(v2 - f23.x, v3 - f23.y);
                *(__nv_bfloat162*)&yh[(size_t)row * 1024 + col] = h01;
                *(__nv_bfloat162*)&yh[(size_t)(row + 8) * 1024 + col] = h23;
                *(__nv_bfloat162*)&yl[(size_t)row * 1024 + col] = l01;
                *(__nv_bfloat162*)&yl[(size_t)(row + 8) * 1024 + col] = l23;
            }
        }
}

// ===========================================================================
// Fused scores + mask + streaming-exp softmax. 16 q-rows x full S.
// k-tile 128, fp16 exp buffer, smem 107.8 KB => 2 blocks/SM for pipe overlap.
// ===========================================================================
constexpr int SCH_STRIDE = 2056;                                 // halves
constexpr int SCH_BYTES  = 16 * SCH_STRIDE * 2;                  // 65792
constexpr int QH_OFF = SCH_BYTES,  QL_OFF = QH_OFF + 16 * 144;   // 65792,68096
constexpr int KH_OFF = QL_OFF + 16 * 144;                        // 70400
constexpr int KL_OFF = KH_OFF + 128 * 144;                       // 88832
constexpr int PS_OFF = KL_OFF + 128 * 144;                       // 107264
constexpr int SMEM_SC = PS_OFF + 8 * 16 * 4;                     // 107776

__global__ __launch_bounds__(256, 2) void scores_softmax(
    const __nv_bfloat16* __restrict__ qh, const __nv_bfloat16* __restrict__ ql,
    const __nv_bfloat16* __restrict__ kh, const __nv_bfloat16* __restrict__ kl,
    const uint32_t* __restrict__ pm, float* __restrict__ aw)
{
    extern __shared__ char sm[];
    __half* sch = (__half*)sm;
    unsigned char* Qh = (unsigned char*)sm + QH_OFF;
    unsigned char* Ql = (unsigned char*)sm + QL_OFF;
    unsigned char* Kh = (unsigned char*)sm + KH_OFF;
    unsigned char* Kl = (unsigned char*)sm + KL_OFF;
    float* psum = (float*)((unsigned char*)sm + PS_OFF);

    const int tid = threadIdx.x, lane = tid & 31, wrp = tid >> 5;
    const int q0 = blockIdx.x * 16;
    const int bh = blockIdx.y;
    const int b = bh >> 4, h = bh & 15;
    const size_t base = (size_t)b * S * D + (size_t)h * DK;
    const int g = lane >> 2, t = lane & 3;

    {
        int f = tid & 127, row = f >> 3, c = f & 7;
        const __nv_bfloat16* src = (tid < 128) ? qh : ql;
        unsigned char* dst = (tid < 128) ? Qh : Ql;
        uint4 v = *(const uint4*)&src[base + (size_t)(q0 + row) * 1024 + c * 8];
        *(uint4*)(dst + row * 144 + c * 16) = v;
    }

    const LdsmIdx ix = ldsm_idx(lane);
    const uint32_t QhS = s2u(Qh), QlS = s2u(Ql), KhS = s2u(Kh), KlS = s2u(Kl);
    const uint32_t aoff = (uint32_t)(ix.a_rel * 144 + ix.a_col);
    const uint32_t boff = (uint32_t)((wrp * 16 + ix.b_which * 8 + ix.b_rel) * 144 + ix.b_sub);

    const uint32_t* pmr0 = pm + ((size_t)b * S + q0 + g) * 64 + (wrp >> 1);
    const uint32_t* pmr1 = pm + ((size_t)b * S + q0 + g + 8) * 64 + (wrp >> 1);
    const int wbase = (wrp & 1) * 16;
    float sum0 = 0.0f, sum1 = 0.0f;

    for (int tile = 0; tile < 16; tile++) {
        const int n0 = tile * 128;
        #pragma unroll
        for (int i = 0; i < 4; i++) {
            int f = tid + i * 256, row = f >> 3, c = f & 7;
            uint4 v = *(const uint4*)&kh[base + (size_t)(n0 + row) * 1024 + c * 8];
            *(uint4*)(Kh + row * 144 + c * 16) = v;
        }
        #pragma unroll
        for (int i = 0; i < 4; i++) {
            int f = tid + i * 256, row = f >> 3, c = f & 7;
            uint4 v = *(const uint4*)&kl[base + (size_t)(n0 + row) * 1024 + c * 8];
            *(uint4*)(Kl + row * 144 + c * 16) = v;
        }
        __syncthreads();

        float acc[2][4];
        #pragma unroll
        for (int nt = 0; nt < 2; nt++)
            #pragma unroll
            for (int r = 0; r < 4; r++) acc[nt][r] = 0.0f;

        #pragma unroll
        for (int ks = 0; ks < 4; ks++) {
            const int ko = ks * 32;
            uint32_t ah[4], al[4], bh2[2][2], bl2[2][2];
            ldsm_x4(ah, QhS + aoff + ko);
            ldsm_x4(al, QlS + aoff + ko);
            {
                uint32_t r4[4];
                ldsm_x4(r4, KhS + boff + ko);
                bh2[0][0] = r4[0]; bh2[0][1] = r4[1];
                bh2[1][0] = r4[2]; bh2[1][1] = r4[3];
                ldsm_x4(r4, KlS + boff + ko);
                bl2[0][0] = r4[0]; bl2[0][1] = r4[1];
                bl2[1][0] = r4[2]; bl2[1][1] = r4[3];
            }
            #pragma unroll
            for (int nt = 0; nt < 2; nt++) {
                mma16816(acc[nt], ah, bh2[nt]);
                mma16816(acc[nt], ah, bl2[nt]);
                mma16816(acc[nt], al, bh2[nt]);
            }
        }

        const uint32_t mw0 = pmr0[tile * 4];
        const uint32_t mw1 = pmr1[tile * 4];
        #pragma unroll
        for (int nt = 0; nt < 2; nt++) {
            const int bit0 = wbase + nt * 8 + 2 * t, bit1 = bit0 + 1;
            float e00 = ((mw0 >> bit0) & 1u) ? 0.0f : __expf(acc[nt][0] * 0.125f);
            float e01 = ((mw0 >> bit1) & 1u) ? 0.0f : __expf(acc[nt][1] * 0.125f);
            float e10 = ((mw1 >> bit0) & 1u) ? 0.0f : __expf(acc[nt][2] * 0.125f);
            float e11 = ((mw1 >> bit1) & 1u) ? 0.0f : __expf(acc[nt][3] * 0.125f);
            sum0 += e00 + e01;
            sum1 += e10 + e11;
            int col = n0 + wrp * 16 + nt * 8 + 2 * t;
            *(__half2*)&sch[g * SCH_STRIDE + col]       = __floats2half2_rn(e00, e01);
            *(__half2*)&sch[(g + 8) * SCH_STRIDE + col] = __floats2half2_rn(e10, e11);
        }
        __syncthreads();
    }

    sum0 += __shfl_xor_sync(0xFFFFFFFFu, sum0, 1);
    sum0 += __shfl_xor_sync(0xFFFFFFFFu, sum0, 2);
    sum1 += __shfl_xor_sync(0xFFFFFFFFu, sum1, 1);
    sum1 += __shfl_xor_sync(0xFFFFFFFFu, sum1, 2);
    if (t == 0) {
        psum[wrp * 16 + g]     = sum0;
        psum[wrp * 16 + g + 8] = sum1;
    }
    __syncthreads();

    #pragma unroll
    for (int rr = 0; rr < 2; rr++) {
        const int r = wrp * 2 + rr, q = q0 + r;
        float tot = 0.0f;
        #pragma unroll
        for (int wv = 0; wv < 8; wv++) tot += psum[wv * 16 + r];
        const float scale = (float)S / tot;
        const __half* srow = &sch[r * SCH_STRIDE];
        float* arow = &aw[((size_t)bh * S + q) * S];
        #pragma unroll
        for (int i = 0; i < 8; i++) {
            int colb = (i * 32 + lane) * 8;
            uint4 packed = *(const uint4*)&srow[colb];
            const __half2* hp = (const __half2*)&packed;
            float4 o0, o1;
            float2 f0 = __half22float2(hp[0]);
            float2 f1 = __half22float2(hp[1]);
            float2 f2 = __half22float2(hp[2]);
            float2 f3 = __half22float2(hp[3]);
            o0.x = f0.x * scale; o0.y = f0.y * scale;
            o0.z = f1.x * scale; o0.w = f1.y * scale;
            o1.x = f2.x * scale; o1.y = f2.y * scale;
            o1.z = f3.x * scale; o1.w = f3.y * scale;
            *(float4*)&arow[colb]     = o0;
            *(float4*)&arow[colb + 4] = o1;
        }
    }
}

// ===========================================================================
// Ctx: block 128q x 64d, K-chunk 64 (R13, unchanged).
// ===========================================================================
__global__ __launch_bounds__(256) void ctx_mma(
    const float* __restrict__ aw,
    const __nv_bfloat16* __restrict__ vth, const __nv_bfloat16* __restrict__ vtl,
    float* __restrict__ ctx)
{
    __shared__ unsigned char Ah[128 * 144], Al[128 * 144], Bh[64 * 144], Bl[64 * 144];
    const int tid = threadIdx.x, lane = tid & 31, wrp = tid >> 5;
    const int q0 = blockIdx.x * 128;
    const int bh = blockIdx.y;
    const int b = bh >> 4, h = bh & 15;
    const size_t vtbase = ((size_t)b * D + h * DK) * S;
    const int wm = (wrp & 3) * 32, wn = (wrp >> 2) * 32;
    const int g = lane >> 2, t = lane & 3;

    float acc[2][4][4];
    #pragma unroll
    for (int i = 0; i < 2; i++)
        #pragma unroll
        for (int j = 0; j < 4; j++)
            #pragma unroll
            for (int r = 0; r < 4; r++) acc[i][j][r] = 0.0f;

    const LdsmIdx ix = ldsm_idx(lane);
    const uint32_t AhS = s2u(Ah), AlS = s2u(Al), BhS = s2u(Bh), BlS = s2u(Bl);
    uint32_t aoff[2], boff[2];
    #pragma unroll
    for (int mt = 0; mt < 2; mt++)
        aoff[mt] = (uint32_t)((wm + mt * 16 + ix.a_rel) * 144 + ix.a_col);
    #pragma unroll
    for (int p = 0; p < 2; p++)
        boff[p] = (uint32_t)((wn + (p * 2 + ix.b_which) * 8 + ix.b_rel) * 144 + ix.b_sub);

    for (int k0 = 0; k0 < S; k0 += 64) {
        #pragma unroll
        for (int i = 0; i < 8; i++) {
            int f = tid + i * 256, row = f >> 4, c = f & 15;
            float4 a = *(const float4*)&aw[((size_t)bh * S + q0 + row) * S + k0 + c * 4];
            uint2 hi, lo; split_f4(a, hi, lo);
            *(uint2*)(Ah + row * 144 + c * 8) = hi;
            *(uint2*)(Al + row * 144 + c * 8) = lo;
        }
        #pragma unroll
        for (int i = 0; i < 2; i++) {
            int f = tid + i * 256, row = f >> 3, c = f & 7;
            uint4 v = *(const uint4*)&vth[vtbase + (size_t)row * S + k0 + c * 8];
            *(uint4*)(Bh + row * 144 + c * 16) = v;
        }
        #pragma unroll
        for (int i = 0; i < 2; i++) {
            int f = tid + i * 256, row = f >> 3, c = f & 7;
            uint4 v = *(const uint4*)&vtl[vtbase + (size_t)row * S + k0 + c * 8];
            *(uint4*)(Bl + row * 144 + c * 16) = v;
        }
        __syncthreads();

        #pragma unroll
        for (int ks = 0; ks < 4; ks++) {
            const int ko = ks * 32;
            uint32_t ah[2][4], al[2][4], bh2[4][2], bl2[4][2];
            #pragma unroll
            for (int mt = 0; mt < 2; mt++) {
                ldsm_x4(ah[mt], AhS + aoff[mt] + ko);
                ldsm_x4(al[mt], AlS + aoff[mt] + ko);
            }
            #pragma unroll
            for (int p = 0; p < 2; p++) {
                uint32_t r4[4];
                ldsm_x4(r4, BhS + boff[p] + ko);
                bh2[2*p][0] = r4[0]; bh2[2*p][1] = r4[1];
                bh2[2*p+1][0] = r4[2]; bh2[2*p+1][1] = r4[3];
                ldsm_x4(r4, BlS + boff[p] + ko);
                bl2[2*p][0] = r4[0]; bl2[2*p][1] = r4[1];
                bl2[2*p+1][0] = r4[2]; bl2[2*p+1][1] = r4[3];
            }
            #pragma unroll
            for (int mt = 0; mt < 2; mt++)
                #pragma unroll
                for (int nt = 0; nt < 4; nt++) {
                    mma16816(acc[mt][nt], ah[mt], bh2[nt]);
                    mma16816(acc[mt][nt], ah[mt], bl2[nt]);
                    mma16816(acc[mt][nt], al[mt], bh2[nt]);
                }
        }
        __syncthreads();
    }

    #pragma unroll
    for (int mt = 0; mt < 2; mt++)
        #pragma unroll
        for (int nt = 0; nt < 4; nt++) {
            int row = q0 + wm + mt * 16 + g;
            int col = wn + nt * 8 + 2 * t;
            *(float2*)&ctx[((size_t)b * S + row) * 1024 + h * DK + col] =
                make_float2(acc[mt][nt][0], acc[mt][nt][1]);
            *(float2*)&ctx[((size_t)b * S + row + 8) * 1024 + h * DK + col] =
                make_float2(acc[mt][nt][2], acc[mt][nt][3]);
        }
}

// ---------------------------------------------------------------------------
extern "C" void kernel_launch(void* const* d_in, const int* in_sizes, int n_in,
                              void* d_out, int out_size)
{
    const float* Q  = (const float*)d_in[0];
    const float* K_ = (const float*)d_in[1];
    const float* V  = (const float*)d_in[2];
    const int*   mask = (const int*)d_in[3];
    const float* Wq = (const float*)d_in[4];
    const float* bq = (const float*)d_in[5];
    const float* Wk = (const float*)d_in[6];
    const float* bk = (const float*)d_in[7];
    const float* Wv = (const float*)d_in[8];
    const float* bv = (const float*)d_in[9];
    const float* Wo = (const float*)d_in[10];
    const float* bo = (const float*)d_in[11];

    __nv_bfloat16 *qh, *ql, *kh, *kl, *vth, *vtl;
    float *gctx, *gaw, *gspill;
    uint32_t* gpm;
    cudaGetSymbolAddress((void**)&qh,   g_qh);
    cudaGetSymbolAddress((void**)&ql,   g_ql);
    cudaGetSymbolAddress((void**)&kh,   g_kh);
    cudaGetSymbolAddress((void**)&kl,   g_kl);
    cudaGetSymbolAddress((void**)&vth,  g_vth);
    cudaGetSymbolAddress((void**)&vtl,  g_vtl);
    cudaGetSymbolAddress((void**)&gctx, g_ctx);
    cudaGetSymbolAddress((void**)&gaw,  g_aw);
    cudaGetSymbolAddress((void**)&gspill, g_out_spill);
    cudaGetSymbolAddress((void**)&gpm,  g_pmask);

    float* out_ptr;
    float* aw_ptr;
    const long long osz = (long long)out_size;
    if (osz >= OUT_ELEMS + AW_ELEMS) {
        out_ptr = (float*)d_out;
        aw_ptr  = (float*)d_out + OUT_ELEMS;
    } else if (osz == AW_ELEMS) {
        out_ptr = gspill;
        aw_ptr  = (float*)d_out;
    } else {
        out_ptr = (float*)d_out;
        aw_ptr  = gaw;
    }

    cudaFuncSetAttribute(scores_softmax, cudaFuncAttributeMaxDynamicSharedMemorySize, SMEM_SC);

    pack_mask<<<1024, 256>>>(mask, gpm);

    dim3 gProj(D / 128, M / 128);                  // (8, 32)
    proj_mma<1><<<gProj, 256>>>(Q,  Wq, bq, nullptr, qh, ql);
    proj_mma<1><<<gProj, 256>>>(K_, Wk, bk, nullptr, kh, kl);
    proj_mma<2><<<gProj, 256>>>(V,  Wv, bv, nullptr, vth, vtl);

    dim3 gSc(S / 16, B * H);                       // (128, 32)
    scores_softmax<<<gSc, 256, SMEM_SC>>>(qh, ql, kh, kl, gpm, aw_ptr);

    dim3 gCx(S / 128, B * H);                      // (16, 32)
    ctx_mma<<<gCx, 256>>>(aw_ptr, vth, vtl, gctx);

    proj_mma<0><<<gProj, 256>>>(gctx, Wo, bo, out_ptr, nullptr, nullptr);
}